// round 4
// baseline (speedup 1.0000x reference)
#include <cuda_runtime.h>
#include <cuda_bf16.h>
#include <math.h>
#include <stdint.h>

#define HH 256
#define WW 256
#define HWSZ 65536
#define BB 2
#define C64 64
#define C128 128
#define C256 256

#define SW128(off) ((off) ^ (((off) >> 3) & 0x70))

__device__ __forceinline__ uint32_t smem_u32(const void* p) {
    uint32_t a;
    asm("{ .reg .u64 t; cvta.to.shared.u64 t, %1; cvt.u32.u64 %0, t; }" : "=r"(a) : "l"(p));
    return a;
}
__device__ __forceinline__ void cpa16(uint32_t dst, const void* src, int sz) {
    asm volatile("cp.async.cg.shared.global [%0], [%1], 16, %2;"
                 :: "r"(dst), "l"(src), "r"(sz) : "memory");
}
__device__ __forceinline__ void cpa_commit() {
    asm volatile("cp.async.commit_group;" ::: "memory");
}
template<int N>
__device__ __forceinline__ void cpa_wait() {
    asm volatile("cp.async.wait_group %0;" :: "n"(N) : "memory");
}
__device__ __forceinline__ void ldm_x4(uint32_t& r0, uint32_t& r1, uint32_t& r2, uint32_t& r3,
                                       uint32_t addr) {
    asm volatile("ldmatrix.sync.aligned.m8n8.x4.shared.b16 {%0,%1,%2,%3}, [%4];"
                 : "=r"(r0), "=r"(r1), "=r"(r2), "=r"(r3) : "r"(addr));
}
__device__ __forceinline__ void mma16816(float* c, const uint32_t* a, uint32_t b0, uint32_t b1) {
    asm volatile("mma.sync.aligned.m16n8k16.row.col.f32.bf16.bf16.f32 "
                 "{%0,%1,%2,%3}, {%4,%5,%6,%7}, {%8,%9}, {%0,%1,%2,%3};"
                 : "+f"(c[0]), "+f"(c[1]), "+f"(c[2]), "+f"(c[3])
                 : "r"(a[0]), "r"(a[1]), "r"(a[2]), "r"(a[3]), "r"(b0), "r"(b1));
}

// ================= scratch (device globals) =================
__device__ float g_up   [BB * C64 * HWSZ];     // upconv out NCHW fp32
__device__ float g_h1raw[BB * HWSZ * C64];     // conv1 raw out NHWC fp32
__device__ float g_b2   [BB * C64 * HWSZ];     // conv2 raw out NCHW fp32
__device__ float g_red[256];                   // [0:64]s1 [64:128]q1 [128:192]s2 [192:256]q2
__device__ float g_ab1[128];
__device__ float g_ab2[128];
__device__ __nv_bfloat16 g_x1_h[BB * 16384 * C64];
__device__ __nv_bfloat16 g_x1_l[BB * 16384 * C64];
__device__ __nv_bfloat16 g_cat_h[BB * HWSZ * C128];
__device__ __nv_bfloat16 g_cat_l[BB * HWSZ * C128];
__device__ __nv_bfloat16 g_xd_h [BB * HWSZ * C128];
__device__ __nv_bfloat16 g_xd_l [BB * HWSZ * C128];
__device__ __nv_bfloat16 g_h1_h [BB * HWSZ * C64];
__device__ __nv_bfloat16 g_h1_l [BB * HWSZ * C64];
__device__ __nv_bfloat16 g_wo_h[18 * C256 * 64];
__device__ __nv_bfloat16 g_wo_l[18 * C256 * 64];
__device__ __nv_bfloat16 g_w1_h[18 * C64 * 64];
__device__ __nv_bfloat16 g_w1_l[18 * C64 * 64];
__device__ __nv_bfloat16 g_w2_h[9 * C64 * 64];
__device__ __nv_bfloat16 g_w2_l[9 * C64 * 64];
__device__ __nv_bfloat16 g_wu_h[C256 * 64];
__device__ __nv_bfloat16 g_wu_l[C256 * 64];

// ================= weight prep: (O,CIN,3,3) -> [kc][o][cc] bf16 hi/lo =================
__global__ void wprep_k(const float* __restrict__ w, __nv_bfloat16* __restrict__ wh,
                        __nv_bfloat16* __restrict__ wl, int N, int CIN)
{
    int i = blockIdx.x * blockDim.x + threadIdx.x;
    if (i >= N * CIN * 9) return;
    int t  = i % 9;
    int ci = (i / 9) % CIN;
    int o  = i / (9 * CIN);
    int q = ci >> 6, cc = ci & 63;
    int kc = t * (CIN >> 6) + q;
    float v = w[i];
    __nv_bfloat16 h = __float2bfloat16(v);
    float lo = v - __bfloat162float(h);
    int dst = (kc * N + o) * 64 + cc;
    wh[dst] = h;
    wl[dst] = __float2bfloat16(lo);
}

// upconv weights (I,O,2,2) -> [n=o*4+k*2+l][cc=i]
__global__ void upwprep_k(const float* __restrict__ w, __nv_bfloat16* __restrict__ wh,
                          __nv_bfloat16* __restrict__ wl)
{
    int s = blockIdx.x * blockDim.x + threadIdx.x;
    if (s >= 64 * 256) return;
    int n = s & 255;
    int cc = s >> 8;
    float v = w[s];
    __nv_bfloat16 h = __float2bfloat16(v);
    float lo = v - __bfloat162float(h);
    wh[n * 64 + cc] = h;
    wl[n * 64 + cc] = __float2bfloat16(lo);
}

// ================= transpose-convert NCHW fp32 -> NHWC bf16 hi/lo =================
// MODE 0: plain C-ch input. MODE 1: concat(in0 64ch, in1 64ch).
template<int C, int MODE, int HWN>
__global__ void __launch_bounds__(256)
tc_k(const float* __restrict__ in0, const float* __restrict__ in1,
     __nv_bfloat16* __restrict__ oh, __nv_bfloat16* __restrict__ ol)
{
    __shared__ float s[C][33];
    const int s0 = blockIdx.x * 32;
    const int b = blockIdx.y;
    const int tid = threadIdx.x;
    const int px = tid & 31;
#pragma unroll 4
    for (int c = tid >> 5; c < C; c += 8) {
        const float* src;
        if (MODE == 1)
            src = (c < 64) ? in0 + (b * 64 + c) * HWN : in1 + (b * 64 + (c - 64)) * HWN;
        else
            src = in0 + (b * C + c) * HWN;
        s[c][px] = src[s0 + px];
    }
    __syncthreads();
#pragma unroll 4
    for (int e = tid; e < 32 * C; e += 256) {
        int p = e / C, c = e % C;
        float v = s[c][p];
        __nv_bfloat16 h = __float2bfloat16(v);
        float lo = v - __bfloat162float(h);
        size_t idx = ((size_t)(b * HWN + s0 + p)) * C + c;
        oh[idx] = h;
        ol[idx] = __float2bfloat16(lo);
    }
}

// ================= upconv via mma: 1x1 GEMM, M=32768, N=256, K=64 =================
__global__ void __launch_bounds__(256, 2)
upmma_k(const __nv_bfloat16* __restrict__ ah_g, const __nv_bfloat16* __restrict__ al_g,
        const __nv_bfloat16* __restrict__ bh_g, const __nv_bfloat16* __restrict__ bl_g,
        const float* __restrict__ upb, float* __restrict__ up)
{
    extern __shared__ char dsm[];
    constexpr int A_H = 0, A_L = 16384, B_H = 32768, B_L = 40960;
    uint32_t raw = smem_u32(dsm);
    uint32_t base = (raw + 1023u) & ~1023u;
    char* smc = dsm + (base - raw);
    const int tid = threadIdx.x;
    const int wid = tid >> 5;
    const int lane = tid & 31;

    const int p0 = blockIdx.x * 128;         // over 2*16384 pixels
    const int b  = p0 >> 14;
    const int sb = p0 & 16383;
    const int y0 = sb >> 7;
    const int oc0 = blockIdx.y * 64;

    // stage A (128 rows x 128B, hi+lo)
#pragma unroll
    for (int it = 0; it < 4; it++) {
        int idx = it * 256 + tid;
        int m = idx >> 3, ch = idx & 7;
        size_t gi = ((size_t)(p0 + m)) * 64 + ch * 8;
        uint32_t sw = SW128(m * 128 + ch * 16);
        cpa16(base + A_H + sw, ah_g + gi, 16);
        cpa16(base + A_L + sw, al_g + gi, 16);
    }
    // stage B (64 rows x 128B, hi+lo)
#pragma unroll
    for (int it = 0; it < 2; it++) {
        int idx = it * 256 + tid;
        int o = idx >> 3, ch = idx & 7;
        size_t gi = ((size_t)(oc0 + o)) * 64 + ch * 8;
        uint32_t sw = SW128(o * 128 + ch * 16);
        cpa16(base + B_H + sw, bh_g + gi, 16);
        cpa16(base + B_L + sw, bl_g + gi, 16);
    }
    cpa_commit();
    cpa_wait<0>();
    __syncthreads();

    float acc[8][4];
#pragma unroll
    for (int g = 0; g < 8; g++)
#pragma unroll
        for (int j = 0; j < 4; j++) acc[g][j] = 0.f;

    const uint32_t Ah = base + A_H, Al = base + A_L;
    const uint32_t Bh = base + B_H, Bl = base + B_L;
    const int arow = wid * 16 + (lane & 15);
    const int nrow = lane & 15;
    const int chalf = (lane >> 4) * 16;
#pragma unroll
    for (int kk = 0; kk < 4; kk++) {
        const int cb = chalf + kk * 32;
        uint32_t ah[4], al[4];
        ldm_x4(ah[0], ah[1], ah[2], ah[3], Ah + SW128(arow * 128 + cb));
        ldm_x4(al[0], al[1], al[2], al[3], Al + SW128(arow * 128 + cb));
#pragma unroll
        for (int g = 0; g < 4; g++) {
            uint32_t off = SW128((g * 16 + nrow) * 128 + cb);
            uint32_t t0, t1, t2, t3, u0, u1, u2, u3;
            ldm_x4(t0, t1, t2, t3, Bh + off);
            ldm_x4(u0, u1, u2, u3, Bl + off);
            mma16816(acc[2 * g],     ah, t0, t2);
            mma16816(acc[2 * g + 1], ah, t1, t3);
            mma16816(acc[2 * g],     al, t0, t2);
            mma16816(acc[2 * g + 1], al, t1, t3);
            mma16816(acc[2 * g],     ah, u0, u2);
            mma16816(acc[2 * g + 1], ah, u1, u3);
        }
    }
    __syncthreads();

    // stage [n][m] then expand to (b,o,2y+k,2x+l)
    float* sepi = (float*)smc;
    const int em = wid * 16 + (lane >> 2);
    const int en = (lane & 3) * 2;
#pragma unroll
    for (int g = 0; g < 8; g++) {
        int n0 = g * 8 + en;
        sepi[n0 * 132 + em]           = acc[g][0];
        sepi[(n0 + 1) * 132 + em]     = acc[g][1];
        sepi[n0 * 132 + em + 8]       = acc[g][2];
        sepi[(n0 + 1) * 132 + em + 8] = acc[g][3];
    }
    __syncthreads();
#pragma unroll 4
    for (int j = 0; j < 32; j++) {
        int lin = j * 256 + tid;       // 0..8191
        int n = lin >> 7, m = lin & 127;
        int ng = oc0 + n;
        int o = ng >> 2, k = (ng >> 1) & 1, l = ng & 1;
        float v = sepi[n * 132 + m] + upb[o];
        up[((size_t)(b * 64 + o) << 16) + (2 * y0 + k) * 256 + 2 * m + l] = v;
    }
}

// ================= mma.sync implicit-GEMM 3x3 conv (bf16x3) =================
// EPI 0: NCHW fp32 + bias + stats(red). EPI 1: NHWC fp32 + bias + stats(red).
// EPI 2: fused deformable gather epilogue -> xd NHWC hi/lo.
template<int NTOT, int NCHUNK, int EPI>
__global__ void __launch_bounds__(256, 2)
convmma_k(const __nv_bfloat16* __restrict__ ah_g, const __nv_bfloat16* __restrict__ al_g,
          const __nv_bfloat16* __restrict__ bh_g, const __nv_bfloat16* __restrict__ bl_g,
          const float* __restrict__ bias, float* __restrict__ out, float* __restrict__ red,
          const float* __restrict__ x2, const float* __restrict__ up,
          __nv_bfloat16* __restrict__ xdh, __nv_bfloat16* __restrict__ xdl)
{
    extern __shared__ char dsm[];
    constexpr int CINQ = NCHUNK / 9;
    constexpr int CCH  = CINQ * 64;
    constexpr int A_H = 0;
    constexpr int A_L = 16384;
    constexpr int B_H = 32768;
    constexpr int B_L = 40960;
    constexpr int STAGE = 49152;

    uint32_t raw = smem_u32(dsm);
    uint32_t base = (raw + 1023u) & ~1023u;
    char* smc = dsm + (base - raw);
    const int tid = threadIdx.x;
    const int wid = tid >> 5;
    const int lane = tid & 31;

    const int p0 = blockIdx.x * 128;
    const int b  = p0 >> 16;
    const int sb = p0 & 65535;
    const int y0 = sb >> 8;
    const int x0 = sb & 255;
    const int oc0 = blockIdx.y * 64;

    auto stage = [&](int kc, int buf) {
        const int t = kc / CINQ;
        const int q = kc - t * CINQ;
        const int ky = t / 3 - 1;
        const int kx = t % 3 - 1;
        const uint32_t sbase = base + buf * STAGE;
        const int yy = y0 + ky;
        const bool yin = (unsigned)yy < 256u;
#pragma unroll
        for (int it = 0; it < 4; it++) {
            int idx = it * 256 + tid;
            int m = idx >> 3, ch = idx & 7;
            int xx = x0 + m + kx;
            bool inb = yin && ((unsigned)xx < 256u);
            size_t gi = (((size_t)b << 16) + (yy << 8) + xx) * CCH + q * 64 + ch * 8;
            if (!inb) gi = 0;
            uint32_t sw = SW128(m * 128 + ch * 16);
            int sz = inb ? 16 : 0;
            cpa16(sbase + A_H + sw, ah_g + gi, sz);
            cpa16(sbase + A_L + sw, al_g + gi, sz);
        }
#pragma unroll
        for (int it = 0; it < 2; it++) {
            int idx = it * 256 + tid;
            int o = idx >> 3, ch = idx & 7;
            size_t gi = ((size_t)kc * NTOT + oc0 + o) * 64 + ch * 8;
            uint32_t sw = SW128(o * 128 + ch * 16);
            cpa16(sbase + B_H + sw, bh_g + gi, 16);
            cpa16(sbase + B_L + sw, bl_g + gi, 16);
        }
        cpa_commit();
    };

    float acc[8][4];
#pragma unroll
    for (int g = 0; g < 8; g++)
#pragma unroll
        for (int j = 0; j < 4; j++) acc[g][j] = 0.f;

    const int mrow = wid * 16;
    stage(0, 0);

#pragma unroll 1
    for (int kc = 0; kc < NCHUNK; kc++) {
        if (kc + 1 < NCHUNK) {
            stage(kc + 1, (kc + 1) & 1);
            cpa_wait<1>();
        } else {
            cpa_wait<0>();
        }
        __syncthreads();

        const uint32_t sbase = base + (kc & 1) * STAGE;
        const uint32_t Ah = sbase + A_H, Al = sbase + A_L;
        const uint32_t Bh = sbase + B_H, Bl = sbase + B_L;
        const int arow = mrow + (lane & 15);
        const int nrow = lane & 15;
        const int chalf = (lane >> 4) * 16;

#pragma unroll
        for (int kk = 0; kk < 4; kk++) {
            const int cb = chalf + kk * 32;
            uint32_t ah[4], al[4];
            ldm_x4(ah[0], ah[1], ah[2], ah[3], Ah + SW128(arow * 128 + cb));
            ldm_x4(al[0], al[1], al[2], al[3], Al + SW128(arow * 128 + cb));
#pragma unroll
            for (int g = 0; g < 4; g++) {
                uint32_t off = SW128((g * 16 + nrow) * 128 + cb);
                uint32_t t0, t1, t2, t3, u0, u1, u2, u3;
                ldm_x4(t0, t1, t2, t3, Bh + off);
                ldm_x4(u0, u1, u2, u3, Bl + off);
                mma16816(acc[2 * g],     ah, t0, t2);
                mma16816(acc[2 * g + 1], ah, t1, t3);
                mma16816(acc[2 * g],     al, t0, t2);
                mma16816(acc[2 * g + 1], al, t1, t3);
                mma16816(acc[2 * g],     ah, u0, u2);
                mma16816(acc[2 * g + 1], ah, u1, u3);
            }
        }
        __syncthreads();
    }

    // ---- stage [n][m] in smem ----
    float* sepi = (float*)smc;
    float* sred = sepi + 64 * 132;             // [2][64][4]
    const int em = wid * 16 + (lane >> 2);
    const int en = (lane & 3) * 2;
#pragma unroll
    for (int g = 0; g < 8; g++) {
        int n0 = g * 8 + en;
        sepi[n0 * 132 + em]           = acc[g][0];
        sepi[(n0 + 1) * 132 + em]     = acc[g][1];
        sepi[n0 * 132 + em + 8]       = acc[g][2];
        sepi[(n0 + 1) * 132 + em + 8] = acc[g][3];
    }
    __syncthreads();

    if (EPI == 0) {
        // NCHW fp32 + bias
#pragma unroll
        for (int j = 0; j < 8; j++) {
            int lin = j * 256 + tid;
            int n = lin >> 5;
            int seg = lin & 31;
            float4 v = *(float4*)(sepi + n * 132 + seg * 4);
            float bz = bias[oc0 + n];
            v.x += bz; v.y += bz; v.z += bz; v.w += bz;
            *(float4*)(out + (((size_t)(b * NTOT + oc0 + n)) << 16) + sb + seg * 4) = v;
        }
    } else if (EPI == 1) {
        // NHWC fp32 + bias
#pragma unroll
        for (int j = 0; j < 8; j++) {
            int lin = j * 256 + tid;
            int m = lin >> 4;
            int cq = lin & 15;
            float4 v;
            v.x = sepi[(cq * 4 + 0) * 132 + m] + bias[cq * 4 + 0];
            v.y = sepi[(cq * 4 + 1) * 132 + m] + bias[cq * 4 + 1];
            v.z = sepi[(cq * 4 + 2) * 132 + m] + bias[cq * 4 + 2];
            v.w = sepi[(cq * 4 + 3) * 132 + m] + bias[cq * 4 + 3];
            *(float4*)(out + ((size_t)(b * 65536 + sb + m)) * 64 + cq * 4) = v;
        }
    } else {
        // fused deformable gather: each even element (q, s) is one gather task
#pragma unroll 1
        for (int it = 0; it < 16; it++) {
            int idx = it * 256 + tid;          // 0..4095
            int ql = idx >> 6;
            int e = idx & 63;
            int m = 2 * e;
            int q = oc0 + ql;
            int c = q >> 1;
            int rem = ((q & 1) << 16) + sb + m;
            int h = rem >> 9;
            int w = (rem >> 1) & 255;
            float oy = sepi[ql * 132 + m];
            float ox = sepi[ql * 132 + m + 1];
            const float* src = (c < 64) ? x2 + ((size_t)(b * 64 + c) << 16)
                                        : up + ((size_t)(b * 64 + c - 64) << 16);
            float cy = fminf(fmaxf(oy + (float)h, 0.f), 255.f);
            float cx = fminf(fmaxf(ox + (float)w, 0.f), 255.f);
            float y0f = floorf(cy), x0f = floorf(cx);
            int iy0 = (int)y0f;
            int ix0 = (int)x0f;
            int iy1 = (int)ceilf(cy);
            int ix1 = (int)ceilf(cx);
            float v00 = src[iy0 * 256 + ix0];
            float v10 = src[iy1 * 256 + ix0];
            float v01 = src[iy0 * 256 + ix1];
            float v11 = src[iy1 * 256 + ix1];
            float wy = cy - y0f, wx = cx - x0f;
            float vt = v00 + (v10 - v00) * wy;
            float vb = v01 + (v11 - v01) * wy;
            float v = vt + (vb - vt) * wx;
            __nv_bfloat16 hi = __float2bfloat16(v);
            float lo = v - __bfloat162float(hi);
            size_t oi = ((size_t)(b * 65536 + h * 256 + w)) * 128 + c;
            xdh[oi] = hi;
            xdl[oi] = __float2bfloat16(lo);
        }
    }

    if (EPI == 0 || EPI == 1) {
        // BN stats: per-thread partial over (n = tid>>2, quarter of m)
        int n = tid >> 2, part = tid & 3;
        float bz = bias[oc0 + n];
        float s1 = 0.f, s2 = 0.f;
        const float* rowp = sepi + n * 132 + part * 32;
#pragma unroll
        for (int j = 0; j < 32; j++) {
            float v = rowp[j] + bz;
            s1 += v;
            s2 = fmaf(v, v, s2);
        }
        sred[(0 * 64 + n) * 4 + part] = s1;
        sred[(1 * 64 + n) * 4 + part] = s2;
        __syncthreads();
        if (tid < 128) {
            int which = tid >> 6, n2 = tid & 63;
            const float* pr = sred + (which * 64 + n2) * 4;
            atomicAdd(red + which * 64 + oc0 + n2, pr[0] + pr[1] + pr[2] + pr[3]);
        }
    }
}

// ================= small kernels =================
__global__ void zero_red_k() { g_red[threadIdx.x] = 0.f; }

__global__ void bnfin_k(const float* __restrict__ red,
                        const float* __restrict__ gamma, const float* __restrict__ beta,
                        float* __restrict__ ab)
{
    int c = threadIdx.x;
    const float invn = 1.f / 131072.f;
    float m = red[c] * invn;
    float var = fmaf(-m, m, red[64 + c] * invn);
    float a = gamma[c] * rsqrtf(var + 1e-5f);
    ab[c] = a;
    ab[64 + c] = fmaf(-m, a, beta[c]);
}

// NHWC fp32 -> affine+relu -> bf16 hi/lo (elementwise, float4)
__global__ void __launch_bounds__(256)
afsplit_k(const float* __restrict__ in, const float* __restrict__ ab,
          __nv_bfloat16* __restrict__ oh, __nv_bfloat16* __restrict__ ol)
{
    int i4 = blockIdx.x * 256 + threadIdx.x;   // 0..2097151
    int c0 = (i4 & 15) * 4;
    float4 v = *(const float4*)(in + (size_t)i4 * 4);
    float vv[4] = {v.x, v.y, v.z, v.w};
    unsigned short hs[4], ls[4];
#pragma unroll
    for (int j = 0; j < 4; j++) {
        int c = c0 + j;
        float y = fmaxf(fmaf(vv[j], __ldg(ab + c), __ldg(ab + 64 + c)), 0.f);
        __nv_bfloat16 hb = __float2bfloat16(y);
        float lo = y - __bfloat162float(hb);
        __nv_bfloat16 lb = __float2bfloat16(lo);
        hs[j] = *(unsigned short*)&hb;
        ls[j] = *(unsigned short*)&lb;
    }
    *(uint2*)((unsigned short*)oh + (size_t)i4 * 4) = *(uint2*)hs;
    *(uint2*)((unsigned short*)ol + (size_t)i4 * 4) = *(uint2*)ls;
}

// final BN+ReLU (NCHW, float4)
__global__ void __launch_bounds__(256)
bnrelu_out_k(const float* __restrict__ buf, const float* __restrict__ ab,
             float* __restrict__ out)
{
    int i4 = blockIdx.x * 256 + threadIdx.x;   // 0..2097151
    int c = (i4 >> 14) & 63;
    float a = __ldg(ab + c), bz = __ldg(ab + 64 + c);
    float4 v = *(const float4*)(buf + (size_t)i4 * 4);
    v.x = fmaxf(fmaf(v.x, a, bz), 0.f);
    v.y = fmaxf(fmaf(v.y, a, bz), 0.f);
    v.z = fmaxf(fmaf(v.z, a, bz), 0.f);
    v.w = fmaxf(fmaf(v.w, a, bz), 0.f);
    *(float4*)(out + (size_t)i4 * 4) = v;
}

// ================= launch =================
extern "C" void kernel_launch(void* const* d_in, const int* in_sizes, int n_in,
                              void* d_out, int out_size)
{
    const float* x1   = (const float*)d_in[0];
    const float* x2   = (const float*)d_in[1];
    const float* up_w = (const float*)d_in[2];
    const float* up_b = (const float*)d_in[3];
    const float* offw = (const float*)d_in[4];
    const float* c1w  = (const float*)d_in[5];
    const float* c1b  = (const float*)d_in[6];
    const float* g1   = (const float*)d_in[7];
    const float* b1   = (const float*)d_in[8];
    const float* c2w  = (const float*)d_in[9];
    const float* c2b  = (const float*)d_in[10];
    const float* g2   = (const float*)d_in[11];
    const float* b2   = (const float*)d_in[12];
    float* outp = (float*)d_out;

    float *p_up, *p_h1raw, *p_b2, *p_red, *p_ab1, *p_ab2;
    cudaGetSymbolAddress((void**)&p_up,    g_up);
    cudaGetSymbolAddress((void**)&p_h1raw, g_h1raw);
    cudaGetSymbolAddress((void**)&p_b2,    g_b2);
    cudaGetSymbolAddress((void**)&p_red,   g_red);
    cudaGetSymbolAddress((void**)&p_ab1,   g_ab1);
    cudaGetSymbolAddress((void**)&p_ab2,   g_ab2);
    __nv_bfloat16 *p_x1_h, *p_x1_l, *p_cat_h, *p_cat_l, *p_xd_h, *p_xd_l, *p_h1_h, *p_h1_l;
    __nv_bfloat16 *p_wo_h, *p_wo_l, *p_w1_h, *p_w1_l, *p_w2_h, *p_w2_l, *p_wu_h, *p_wu_l;
    cudaGetSymbolAddress((void**)&p_x1_h, g_x1_h);
    cudaGetSymbolAddress((void**)&p_x1_l, g_x1_l);
    cudaGetSymbolAddress((void**)&p_cat_h, g_cat_h);
    cudaGetSymbolAddress((void**)&p_cat_l, g_cat_l);
    cudaGetSymbolAddress((void**)&p_xd_h, g_xd_h);
    cudaGetSymbolAddress((void**)&p_xd_l, g_xd_l);
    cudaGetSymbolAddress((void**)&p_h1_h, g_h1_h);
    cudaGetSymbolAddress((void**)&p_h1_l, g_h1_l);
    cudaGetSymbolAddress((void**)&p_wo_h, g_wo_h);
    cudaGetSymbolAddress((void**)&p_wo_l, g_wo_l);
    cudaGetSymbolAddress((void**)&p_w1_h, g_w1_h);
    cudaGetSymbolAddress((void**)&p_w1_l, g_w1_l);
    cudaGetSymbolAddress((void**)&p_w2_h, g_w2_h);
    cudaGetSymbolAddress((void**)&p_w2_l, g_w2_l);
    cudaGetSymbolAddress((void**)&p_wu_h, g_wu_h);
    cudaGetSymbolAddress((void**)&p_wu_l, g_wu_l);

    const int smem_mm = 2 * 49152 + 1024;
    const int smem_up = 49152 + 1024;
    cudaFuncSetAttribute(convmma_k<256, 18, 2>, cudaFuncAttributeMaxDynamicSharedMemorySize, smem_mm);
    cudaFuncSetAttribute(convmma_k<64, 18, 1>,  cudaFuncAttributeMaxDynamicSharedMemorySize, smem_mm);
    cudaFuncSetAttribute(convmma_k<64, 9, 0>,   cudaFuncAttributeMaxDynamicSharedMemorySize, smem_mm);
    cudaFuncSetAttribute(upmma_k, cudaFuncAttributeMaxDynamicSharedMemorySize, smem_up);

    // 0) zero stats + weight prep
    zero_red_k<<<1, 256>>>();
    wprep_k<<<(256 * 128 * 9 + 255) / 256, 256>>>(offw, p_wo_h, p_wo_l, 256, 128);
    wprep_k<<<(64 * 128 * 9 + 255) / 256, 256>>>(c1w, p_w1_h, p_w1_l, 64, 128);
    wprep_k<<<(64 * 64 * 9 + 255) / 256, 256>>>(c2w, p_w2_h, p_w2_l, 64, 64);
    upwprep_k<<<64, 256>>>(up_w, p_wu_h, p_wu_l);

    // 1) x1 -> NHWC hi/lo, then upconv via mma
    tc_k<64, 0, 16384><<<dim3(512, 2), 256>>>(x1, nullptr, p_x1_h, p_x1_l);
    upmma_k<<<dim3(256, 4), 256, smem_up>>>(p_x1_h, p_x1_l, p_wu_h, p_wu_l, up_b, p_up);

    // 2) concat -> NHWC bf16 hi/lo
    tc_k<128, 1, 65536><<<dim3(2048, 2), 256>>>(x2, p_up, p_cat_h, p_cat_l);

    // 3) offset conv + fused deformable gather -> xd NHWC hi/lo
    convmma_k<256, 18, 2><<<dim3(1024, 4), 256, smem_mm>>>(
        p_cat_h, p_cat_l, p_wo_h, p_wo_l, nullptr, nullptr, nullptr,
        x2, p_up, p_xd_h, p_xd_l);

    // 4) conv1 -> NHWC fp32 + fused BN1 stats
    convmma_k<64, 18, 1><<<dim3(1024, 1), 256, smem_mm>>>(
        p_xd_h, p_xd_l, p_w1_h, p_w1_l, c1b, p_h1raw, p_red,
        nullptr, nullptr, nullptr, nullptr);
    bnfin_k<<<1, 64>>>(p_red, g1, b1, p_ab1);

    // 5) BN1 affine + relu + split (elementwise NHWC)
    afsplit_k<<<8192, 256>>>(p_h1raw, p_ab1, p_h1_h, p_h1_l);

    // 6) conv2 -> NCHW fp32 + fused BN2 stats
    convmma_k<64, 9, 0><<<dim3(1024, 1), 256, smem_mm>>>(
        p_h1_h, p_h1_l, p_w2_h, p_w2_l, c2b, p_b2, p_red + 128,
        nullptr, nullptr, nullptr, nullptr);
    bnfin_k<<<1, 64>>>(p_red + 128, g2, b2, p_ab2);

    // 7) final BN+ReLU
    bnrelu_out_k<<<8192, 256>>>(p_b2, p_ab2, outp);
}